// round 1
// baseline (speedup 1.0000x reference)
#include <cuda_runtime.h>

#define N_NODES 50000
#define N_EDGES 1600000
#define CDIM 128
#define N_LAYERS 8

// ---------------- scratch (device globals; no allocation allowed) ----------
__device__ float g_h [N_NODES * CDIM];
__device__ float g_hw[N_NODES * CDIM];
__device__ float g_A [N_NODES * CDIM];
__device__ float g_B [N_NODES * CDIM];
__device__ float g_dis[N_NODES];
__device__ int   g_deg[N_NODES];
__device__ int   g_indptr[N_NODES + 1];
__device__ int   g_cursor[N_NODES];
__device__ int   g_csr_src[N_EDGES];
__device__ float g_csr_nrm[N_EDGES];

// ---------------- small helpers --------------------------------------------
__device__ __forceinline__ float4 f4add(float4 a, float4 b) {
    return make_float4(a.x + b.x, a.y + b.y, a.z + b.z, a.w + b.w);
}
__device__ __forceinline__ float4 f4relu(float4 a) {
    return make_float4(fmaxf(a.x, 0.f), fmaxf(a.y, 0.f), fmaxf(a.z, 0.f), fmaxf(a.w, 0.f));
}

// ---------------- setup kernels ---------------------------------------------
__global__ void k_zero_deg() {
    int i = blockIdx.x * blockDim.x + threadIdx.x;
    if (i < N_NODES) g_deg[i] = 0;
}

__global__ void k_count_deg(const int* __restrict__ col) {
    int e = blockIdx.x * blockDim.x + threadIdx.x;
    if (e < N_EDGES) atomicAdd(&g_deg[col[e]], 1);
}

// single-block exclusive scan over degrees -> indptr/cursor; also dis = rsqrt(deg+1)
__global__ void k_scan_dis() {
    __shared__ int sbuf[1024];
    __shared__ int s_carry;
    int t = threadIdx.x;
    if (t == 0) s_carry = 0;
    __syncthreads();
    for (int base = 0; base < N_NODES; base += 1024) {
        int idx = base + t;
        int v = (idx < N_NODES) ? g_deg[idx] : 0;
        sbuf[t] = v;
        __syncthreads();
        for (int off = 1; off < 1024; off <<= 1) {
            int y = (t >= off) ? sbuf[t - off] : 0;
            __syncthreads();
            sbuf[t] += y;
            __syncthreads();
        }
        int incl = sbuf[t];
        int carry = s_carry;
        if (idx < N_NODES) {
            int excl = carry + incl - v;
            g_indptr[idx] = excl;
            g_cursor[idx] = excl;
            g_dis[idx] = rsqrtf((float)(v + 1));  // +1 self loop
        }
        __syncthreads();
        if (t == 1023) s_carry = carry + sbuf[1023];
        __syncthreads();
    }
    if (t == 0) g_indptr[N_NODES] = s_carry;
}

__global__ void k_fill_csr(const int* __restrict__ row, const int* __restrict__ col) {
    int e = blockIdx.x * blockDim.x + threadIdx.x;
    if (e < N_EDGES) {
        int r = row[e], c = col[e];
        float nrm = g_dis[r] * g_dis[c];
        int pos = atomicAdd(&g_cursor[c], 1);
        g_csr_src[pos] = r;
        g_csr_nrm[pos] = nrm;
    }
}

// ---------------- SGEMM: out[M,128] = Ain[M,128] @ W[128,128] (+bias) -------
// 256 threads, tile M=64, full N=128, full K=128 in smem.
__global__ void k_sgemm(const float* __restrict__ Aext, int a_sel, int out_sel,
                        const float* __restrict__ W, const float* __restrict__ bias,
                        int M) {
    extern __shared__ float sm[];
    float* As = sm;             // 64*128
    float* Ws = sm + 64 * 128;  // 128*128
    const float* Ain = a_sel ? g_h : Aext;
    float* out = (out_sel == 0) ? g_hw : (out_sel == 1 ? g_A : g_B);

    int t = threadIdx.x;
    int tx = t & 31, ty = t >> 5;
    int rowBase = blockIdx.x * 64;

    const float4* W4 = (const float4*)W;
    float4* Ws4 = (float4*)Ws;
#pragma unroll
    for (int i = 0; i < 16; i++) Ws4[t + 256 * i] = W4[t + 256 * i];

    const float4* A4 = (const float4*)Ain;
    float4* As4 = (float4*)As;
#pragma unroll
    for (int i = 0; i < 8; i++) {
        int idx = t + 256 * i;      // float4 index, 32 per row
        int rr = idx >> 5;
        int cc = idx & 31;
        float4 val = make_float4(0.f, 0.f, 0.f, 0.f);
        if (rowBase + rr < M) val = A4[(rowBase + rr) * 32 + cc];
        As4[idx] = val;
    }
    __syncthreads();

    float acc[8][4];
#pragma unroll
    for (int r = 0; r < 8; r++)
#pragma unroll
        for (int j = 0; j < 4; j++) acc[r][j] = 0.f;

#pragma unroll 4
    for (int k = 0; k < 128; k += 4) {
        float4 b0 = Ws4[(k + 0) * 32 + tx];
        float4 b1 = Ws4[(k + 1) * 32 + tx];
        float4 b2 = Ws4[(k + 2) * 32 + tx];
        float4 b3 = Ws4[(k + 3) * 32 + tx];
#pragma unroll
        for (int r = 0; r < 8; r++) {
            float4 a = As4[(ty * 8 + r) * 32 + (k >> 2)];
            acc[r][0] += a.x * b0.x + a.y * b1.x + a.z * b2.x + a.w * b3.x;
            acc[r][1] += a.x * b0.y + a.y * b1.y + a.z * b2.y + a.w * b3.y;
            acc[r][2] += a.x * b0.z + a.y * b1.z + a.z * b2.z + a.w * b3.z;
            acc[r][3] += a.x * b0.w + a.y * b1.w + a.z * b2.w + a.w * b3.w;
        }
    }

    float4 bv = make_float4(0.f, 0.f, 0.f, 0.f);
    if (bias) bv = ((const float4*)bias)[tx];
    float4* out4 = (float4*)out;
#pragma unroll
    for (int r = 0; r < 8; r++) {
        int rr = rowBase + ty * 8 + r;
        if (rr < M) {
            float4 o = make_float4(acc[r][0] + bv.x, acc[r][1] + bv.y,
                                   acc[r][2] + bv.z, acc[r][3] + bv.w);
            out4[rr * 32 + tx] = o;
        }
    }
}

// ---------------- aggregation: h[n] = relu(self + sum + bias (+res)) --------
// one warp per node, lane owns one float4 (4 channels)
__global__ void k_agg(const float* __restrict__ bias, int residual) {
    int gw = (blockIdx.x * blockDim.x + threadIdx.x) >> 5;
    int lane = threadIdx.x & 31;
    if (gw >= N_NODES) return;
    int n = gw;

    const float4* hw4 = (const float4*)g_hw;
    float d = g_dis[n];
    float ds = d * d;
    float4 v = hw4[n * 32 + lane];
    float4 acc = make_float4(v.x * ds, v.y * ds, v.z * ds, v.w * ds);

    int e = g_indptr[n];
    int end = g_indptr[n + 1];
    for (; e + 4 <= end; e += 4) {
        int s0 = g_csr_src[e + 0], s1 = g_csr_src[e + 1];
        int s2 = g_csr_src[e + 2], s3 = g_csr_src[e + 3];
        float n0 = g_csr_nrm[e + 0], n1 = g_csr_nrm[e + 1];
        float n2 = g_csr_nrm[e + 2], n3 = g_csr_nrm[e + 3];
        float4 v0 = hw4[s0 * 32 + lane];
        float4 v1 = hw4[s1 * 32 + lane];
        float4 v2 = hw4[s2 * 32 + lane];
        float4 v3 = hw4[s3 * 32 + lane];
        acc.x += n0 * v0.x + n1 * v1.x + n2 * v2.x + n3 * v3.x;
        acc.y += n0 * v0.y + n1 * v1.y + n2 * v2.y + n3 * v3.y;
        acc.z += n0 * v0.z + n1 * v1.z + n2 * v2.z + n3 * v3.z;
        acc.w += n0 * v0.w + n1 * v1.w + n2 * v2.w + n3 * v3.w;
    }
    for (; e < end; e++) {
        int s = g_csr_src[e];
        float nr = g_csr_nrm[e];
        float4 vv = hw4[s * 32 + lane];
        acc.x += nr * vv.x; acc.y += nr * vv.y;
        acc.z += nr * vv.z; acc.w += nr * vv.w;
    }

    float4 b = ((const float4*)bias)[lane];
    acc = f4add(acc, b);
    if (residual) {
        float4 hp = ((const float4*)g_h)[n * 32 + lane];
        acc = f4add(acc, hp);
    }
    ((float4*)g_h)[n * 32 + lane] = f4relu(acc);
}

// ---------------- fused edge MLP --------------------------------------------
// u = relu(A[row]+B[col]); v = relu(u @ W1 + b1); out = v . w2 + b2
// 64 edges per CTA, 256 threads. fc0 already folded into A/B.
__global__ void k_edge_mlp(const int* __restrict__ row, const int* __restrict__ col,
                           const float* __restrict__ W1, const float* __restrict__ b1,
                           const float* __restrict__ w2, const float* __restrict__ b2,
                           float* __restrict__ out) {
    extern __shared__ float sm[];
    float* Us  = sm;                      // 64*128
    float* W1s = sm + 64 * 128;           // 128*128
    float* w2s = W1s + 128 * 128;         // 128
    float* b1s = w2s + 128;               // 128

    int t = threadIdx.x;
    int tx = t & 31, ty = t >> 5;

    const float4* W14 = (const float4*)W1;
    float4* W1s4 = (float4*)W1s;
#pragma unroll
    for (int i = 0; i < 16; i++) W1s4[t + 256 * i] = W14[t + 256 * i];
    if (t < 32) {
        ((float4*)w2s)[t] = ((const float4*)w2)[t];
        ((float4*)b1s)[t] = ((const float4*)b1)[t];
    }

    int ebase = blockIdx.x * 64;
    {
        int i = t >> 2, p = t & 3;        // edge i, quarter p
        int eidx = ebase + i;
        if (eidx < N_EDGES) {
            int r = row[eidx], c = col[eidx];
            const float4* A4 = (const float4*)g_A;
            const float4* B4 = (const float4*)g_B;
            float4* Us4 = (float4*)Us;
#pragma unroll
            for (int q = 0; q < 8; q++) {
                int cc = p * 8 + q;       // float4 col 0..31
                float4 u = f4relu(f4add(A4[r * 32 + cc], B4[c * 32 + cc]));
                Us4[i * 32 + cc] = u;
            }
        }
    }
    __syncthreads();

    const float4* Us4 = (const float4*)Us;
    float acc[8][4];
#pragma unroll
    for (int r = 0; r < 8; r++)
#pragma unroll
        for (int j = 0; j < 4; j++) acc[r][j] = 0.f;

#pragma unroll 4
    for (int k = 0; k < 128; k += 4) {
        float4 b0 = W1s4[(k + 0) * 32 + tx];
        float4 b1v = W1s4[(k + 1) * 32 + tx];
        float4 b2v = W1s4[(k + 2) * 32 + tx];
        float4 b3v = W1s4[(k + 3) * 32 + tx];
#pragma unroll
        for (int r = 0; r < 8; r++) {
            float4 a = Us4[(ty * 8 + r) * 32 + (k >> 2)];
            acc[r][0] += a.x * b0.x + a.y * b1v.x + a.z * b2v.x + a.w * b3v.x;
            acc[r][1] += a.x * b0.y + a.y * b1v.y + a.z * b2v.y + a.w * b3v.y;
            acc[r][2] += a.x * b0.z + a.y * b1v.z + a.z * b2v.z + a.w * b3v.z;
            acc[r][3] += a.x * b0.w + a.y * b1v.w + a.z * b2v.w + a.w * b3v.w;
        }
    }

    float4 bv = ((const float4*)b1s)[tx];
    float4 w2v = ((const float4*)w2s)[tx];
    float bias2 = b2[0];
#pragma unroll
    for (int r = 0; r < 8; r++) {
        float vx = fmaxf(acc[r][0] + bv.x, 0.f);
        float vy = fmaxf(acc[r][1] + bv.y, 0.f);
        float vz = fmaxf(acc[r][2] + bv.z, 0.f);
        float vw = fmaxf(acc[r][3] + bv.w, 0.f);
        float p = vx * w2v.x + vy * w2v.y + vz * w2v.z + vw * w2v.w;
#pragma unroll
        for (int off = 16; off > 0; off >>= 1)
            p += __shfl_xor_sync(0xffffffffu, p, off);
        if (tx == 0) {
            int eidx = ebase + ty * 8 + r;
            if (eidx < N_EDGES) out[eidx] = p + bias2;
        }
    }
}

// ---------------- launch -----------------------------------------------------
extern "C" void kernel_launch(void* const* d_in, const int* in_sizes, int n_in,
                              void* d_out, int out_size) {
    const float* x       = (const float*)d_in[0];
    const int*   ei      = (const int*)d_in[1];
    const float* convs_W = (const float*)d_in[2];
    const float* convs_b = (const float*)d_in[3];
    const float* fc0_W   = (const float*)d_in[4];
    const float* fc0_b   = (const float*)d_in[5];
    const float* fc1_W   = (const float*)d_in[6];
    const float* fc1_b   = (const float*)d_in[7];
    const float* fc2_W   = (const float*)d_in[8];
    const float* fc2_b   = (const float*)d_in[9];
    float* out = (float*)d_out;

    const int* row = ei;
    const int* col = ei + N_EDGES;

    const int SMEM_GEMM = (64 * 128 + 128 * 128) * 4;          // 98304
    const int SMEM_EDGE = (64 * 128 + 128 * 128 + 256) * 4;    // 99328
    cudaFuncSetAttribute(k_sgemm,    cudaFuncAttributeMaxDynamicSharedMemorySize, SMEM_GEMM);
    cudaFuncSetAttribute(k_edge_mlp, cudaFuncAttributeMaxDynamicSharedMemorySize, SMEM_EDGE);

    // 1. degree / dis / CSR
    k_zero_deg<<<(N_NODES + 255) / 256, 256>>>();
    k_count_deg<<<(N_EDGES + 255) / 256, 256>>>(col);
    k_scan_dis<<<1, 1024>>>();
    k_fill_csr<<<(N_EDGES + 255) / 256, 256>>>(row, col);

    // 2. GCN layers
    const int GRID_GEMM = (N_NODES + 63) / 64;
    for (int l = 0; l < N_LAYERS; l++) {
        const float* W = convs_W + l * CDIM * CDIM;
        const float* b = convs_b + l * CDIM;
        k_sgemm<<<GRID_GEMM, 256, SMEM_GEMM>>>(x, (l == 0) ? 0 : 1, /*out=g_hw*/0,
                                               W, nullptr, N_NODES);
        k_agg<<<(N_NODES * 32 + 255) / 256, 256>>>(b, (l == 0) ? 0 : 1);
    }

    // 3. factorized fc0: A = h@W0a + b0, B = h@W0b
    k_sgemm<<<GRID_GEMM, 256, SMEM_GEMM>>>(nullptr, 1, /*out=g_A*/1,
                                           fc0_W, fc0_b, N_NODES);
    k_sgemm<<<GRID_GEMM, 256, SMEM_GEMM>>>(nullptr, 1, /*out=g_B*/2,
                                           fc0_W + CDIM * CDIM, nullptr, N_NODES);

    // 4. fused edge MLP
    k_edge_mlp<<<(N_EDGES + 63) / 64, 256, SMEM_EDGE>>>(row, col, fc1_W, fc1_b,
                                                        fc2_W, fc2_b, out);
}

// round 3
// speedup vs baseline: 1.5002x; 1.5002x over previous
#include <cuda_runtime.h>
#include <cstdint>

#define N_NODES 50000
#define N_EDGES 1600000
#define CDIM 128
#define N_LAYERS 8

// ---------------- scratch (device globals; no allocation allowed) ----------
__device__ float g_h [N_NODES * CDIM];
__device__ float g_hw[N_NODES * CDIM];
__device__ float g_A [N_NODES * CDIM];
__device__ float g_B [N_NODES * CDIM];
__device__ float g_dis[N_NODES];
__device__ int   g_deg[N_NODES];
__device__ int   g_indptr[N_NODES + 1];
__device__ int   g_cursor[N_NODES];
__device__ int   g_csr_src[N_EDGES];
__device__ float g_csr_nrm[N_EDGES];

// ---------------- helpers ----------------------------------------------------
__device__ __forceinline__ uint32_t f2tf32(float f) {
    uint32_t r;
    asm("cvt.rna.tf32.f32 %0, %1;" : "=r"(r) : "f"(f));
    return r;
}
__device__ __forceinline__ void mma_tf32(float d[4], const uint32_t a[4],
                                         uint32_t b0, uint32_t b1) {
    asm volatile(
        "mma.sync.aligned.m16n8k8.row.col.f32.tf32.tf32.f32 "
        "{%0,%1,%2,%3}, {%4,%5,%6,%7}, {%8,%9}, {%0,%1,%2,%3};"
        : "+f"(d[0]), "+f"(d[1]), "+f"(d[2]), "+f"(d[3])
        : "r"(a[0]), "r"(a[1]), "r"(a[2]), "r"(a[3]), "r"(b0), "r"(b1));
}
__device__ __forceinline__ float4 f4add(float4 a, float4 b) {
    return make_float4(a.x + b.x, a.y + b.y, a.z + b.z, a.w + b.w);
}
__device__ __forceinline__ float4 f4relu(float4 a) {
    return make_float4(fmaxf(a.x, 0.f), fmaxf(a.y, 0.f), fmaxf(a.z, 0.f), fmaxf(a.w, 0.f));
}

// ---------------- setup kernels ---------------------------------------------
__global__ void k_zero_deg() {
    int i = blockIdx.x * blockDim.x + threadIdx.x;
    if (i < N_NODES) g_deg[i] = 0;
}

__global__ void k_count_deg(const int* __restrict__ col) {
    int e = blockIdx.x * blockDim.x + threadIdx.x;
    if (e < N_EDGES) atomicAdd(&g_deg[col[e]], 1);
}

__global__ void k_scan_dis() {
    __shared__ int sbuf[1024];
    __shared__ int s_carry;
    int t = threadIdx.x;
    if (t == 0) s_carry = 0;
    __syncthreads();
    for (int base = 0; base < N_NODES; base += 1024) {
        int idx = base + t;
        int v = (idx < N_NODES) ? g_deg[idx] : 0;
        sbuf[t] = v;
        __syncthreads();
        for (int off = 1; off < 1024; off <<= 1) {
            int y = (t >= off) ? sbuf[t - off] : 0;
            __syncthreads();
            sbuf[t] += y;
            __syncthreads();
        }
        int incl = sbuf[t];
        int carry = s_carry;
        if (idx < N_NODES) {
            int excl = carry + incl - v;
            g_indptr[idx] = excl;
            g_cursor[idx] = excl;
            g_dis[idx] = rsqrtf((float)(v + 1));
        }
        __syncthreads();
        if (t == 1023) s_carry = carry + sbuf[1023];
        __syncthreads();
    }
    if (t == 0) g_indptr[N_NODES] = s_carry;
}

__global__ void k_fill_csr(const int* __restrict__ row, const int* __restrict__ col) {
    int e = blockIdx.x * blockDim.x + threadIdx.x;
    if (e < N_EDGES) {
        int r = row[e], c = col[e];
        float nrm = g_dis[r] * g_dis[c];
        int pos = atomicAdd(&g_cursor[c], 1);
        g_csr_src[pos] = r;
        g_csr_nrm[pos] = nrm;
    }
}

// ---------------- SGEMM: out[M,128] = Ain[M,128] @ W[128,128] (+bias) -------
__global__ void k_sgemm(const float* __restrict__ Aext, int a_sel, int out_sel,
                        const float* __restrict__ W, const float* __restrict__ bias,
                        int M) {
    extern __shared__ float sm[];
    float* As = sm;
    float* Ws = sm + 64 * 128;
    const float* Ain = a_sel ? g_h : Aext;
    float* out = (out_sel == 0) ? g_hw : (out_sel == 1 ? g_A : g_B);

    int t = threadIdx.x;
    int tx = t & 31, ty = t >> 5;
    int rowBase = blockIdx.x * 64;

    const float4* W4 = (const float4*)W;
    float4* Ws4 = (float4*)Ws;
#pragma unroll
    for (int i = 0; i < 16; i++) Ws4[t + 256 * i] = W4[t + 256 * i];

    const float4* A4 = (const float4*)Ain;
    float4* As4 = (float4*)As;
#pragma unroll
    for (int i = 0; i < 8; i++) {
        int idx = t + 256 * i;
        int rr = idx >> 5;
        int cc = idx & 31;
        float4 val = make_float4(0.f, 0.f, 0.f, 0.f);
        if (rowBase + rr < M) val = A4[(rowBase + rr) * 32 + cc];
        As4[idx] = val;
    }
    __syncthreads();

    float acc[8][4];
#pragma unroll
    for (int r = 0; r < 8; r++)
#pragma unroll
        for (int j = 0; j < 4; j++) acc[r][j] = 0.f;

#pragma unroll 4
    for (int k = 0; k < 128; k += 4) {
        float4 b0 = Ws4[(k + 0) * 32 + tx];
        float4 b1 = Ws4[(k + 1) * 32 + tx];
        float4 b2 = Ws4[(k + 2) * 32 + tx];
        float4 b3 = Ws4[(k + 3) * 32 + tx];
#pragma unroll
        for (int r = 0; r < 8; r++) {
            float4 a = As4[(ty * 8 + r) * 32 + (k >> 2)];
            acc[r][0] += a.x * b0.x + a.y * b1.x + a.z * b2.x + a.w * b3.x;
            acc[r][1] += a.x * b0.y + a.y * b1.y + a.z * b2.y + a.w * b3.y;
            acc[r][2] += a.x * b0.z + a.y * b1.z + a.z * b2.z + a.w * b3.z;
            acc[r][3] += a.x * b0.w + a.y * b1.w + a.z * b2.w + a.w * b3.w;
        }
    }

    float4 bv = make_float4(0.f, 0.f, 0.f, 0.f);
    if (bias) bv = ((const float4*)bias)[tx];
    float4* out4 = (float4*)out;
#pragma unroll
    for (int r = 0; r < 8; r++) {
        int rr = rowBase + ty * 8 + r;
        if (rr < M) {
            float4 o = make_float4(acc[r][0] + bv.x, acc[r][1] + bv.y,
                                   acc[r][2] + bv.z, acc[r][3] + bv.w);
            out4[rr * 32 + tx] = o;
        }
    }
}

// ---------------- aggregation: h[n] = relu(self + sum + bias (+res)) --------
__global__ void k_agg(const float* __restrict__ bias, int residual) {
    int gw = (blockIdx.x * blockDim.x + threadIdx.x) >> 5;
    int lane = threadIdx.x & 31;
    if (gw >= N_NODES) return;
    int n = gw;

    const float4* hw4 = (const float4*)g_hw;
    float d = g_dis[n];
    float ds = d * d;
    float4 v = hw4[n * 32 + lane];
    float4 acc = make_float4(v.x * ds, v.y * ds, v.z * ds, v.w * ds);

    int e = g_indptr[n];
    int end = g_indptr[n + 1];
    for (; e + 4 <= end; e += 4) {
        int s0 = g_csr_src[e + 0], s1 = g_csr_src[e + 1];
        int s2 = g_csr_src[e + 2], s3 = g_csr_src[e + 3];
        float n0 = g_csr_nrm[e + 0], n1 = g_csr_nrm[e + 1];
        float n2 = g_csr_nrm[e + 2], n3 = g_csr_nrm[e + 3];
        float4 v0 = hw4[s0 * 32 + lane];
        float4 v1 = hw4[s1 * 32 + lane];
        float4 v2 = hw4[s2 * 32 + lane];
        float4 v3 = hw4[s3 * 32 + lane];
        acc.x += n0 * v0.x + n1 * v1.x + n2 * v2.x + n3 * v3.x;
        acc.y += n0 * v0.y + n1 * v1.y + n2 * v2.y + n3 * v3.y;
        acc.z += n0 * v0.z + n1 * v1.z + n2 * v2.z + n3 * v3.z;
        acc.w += n0 * v0.w + n1 * v1.w + n2 * v2.w + n3 * v3.w;
    }
    for (; e < end; e++) {
        int s = g_csr_src[e];
        float nr = g_csr_nrm[e];
        float4 vv = hw4[s * 32 + lane];
        acc.x += nr * vv.x; acc.y += nr * vv.y;
        acc.z += nr * vv.z; acc.w += nr * vv.w;
    }

    float4 b = ((const float4*)bias)[lane];
    acc = f4add(acc, b);
    if (residual) {
        float4 hp = ((const float4*)g_h)[n * 32 + lane];
        acc = f4add(acc, hp);
    }
    ((float4*)g_h)[n * 32 + lane] = f4relu(acc);
}

// ---------------- fused edge MLP on tensor cores (mma.sync tf32) ------------
// CTA: 128 edges x 128 hidden, 256 threads / 8 warps.
// Warp tile m32 x n64: warp (rblk = wid>>1, cblk = wid&1).
// u = relu(A[row]+B[col]) -> smem Us (stride 132: conflict-free A frags)
// W1 (tf32)              -> smem Ws (stride 136: conflict-free B frags)
// out[e] = relu(u @ W1 + b1) . w2 + b2; cross-warp combine via pbuf.
#define US_STRIDE 132
#define WS_STRIDE 136
#define SMEM_EDGE_FLOATS (128 * US_STRIDE + 128 * WS_STRIDE + 128 + 128 + 256)

__global__ void __launch_bounds__(256, 1) k_edge_mlp_mma(
    const int* __restrict__ row, const int* __restrict__ col,
    const float* __restrict__ W1, const float* __restrict__ b1,
    const float* __restrict__ w2, const float* __restrict__ b2,
    float* __restrict__ out) {
    extern __shared__ float sm[];
    float* Us   = sm;                         // 128 x 132
    float* Ws   = Us + 128 * US_STRIDE;       // 128 x 136 (tf32 bits)
    float* b1s  = Ws + 128 * WS_STRIDE;       // 128
    float* w2s  = b1s + 128;                  // 128
    float* pbuf = w2s + 128;                  // 2 x 128

    int tid = threadIdx.x;
    int lane = tid & 31, wid = tid >> 5;

    // --- W1 -> Ws (tf32), b1/w2 -> smem -------------------------------------
    uint32_t* Wsu = (uint32_t*)Ws;
#pragma unroll
    for (int it = 0; it < 64; it++) {
        int i = it * 256 + tid;
        int kk = i >> 7, n = i & 127;
        Wsu[kk * WS_STRIDE + n] = f2tf32(W1[i]);
    }
    if (tid < 128) { b1s[tid] = b1[tid]; w2s[tid] = w2[tid]; }

    // --- gather u = relu(A[row]+B[col]) into Us (tf32) -----------------------
    int e0 = blockIdx.x * 128;
    {
        int i = tid >> 1, h = tid & 1;
        int r = row[e0 + i] * 32, c = col[e0 + i] * 32;
        const float4* A4 = (const float4*)g_A;
        const float4* B4 = (const float4*)g_B;
        uint32_t* dst = (uint32_t*)(Us + i * US_STRIDE + h * 64);
#pragma unroll
        for (int q = 0; q < 16; q++) {
            float4 a = A4[r + h * 16 + q];
            float4 b = B4[c + h * 16 + q];
            dst[q * 4 + 0] = f2tf32(fmaxf(a.x + b.x, 0.f));
            dst[q * 4 + 1] = f2tf32(fmaxf(a.y + b.y, 0.f));
            dst[q * 4 + 2] = f2tf32(fmaxf(a.z + b.z, 0.f));
            dst[q * 4 + 3] = f2tf32(fmaxf(a.w + b.w, 0.f));
        }
    }
    __syncthreads();

    // --- mma mainloop ---------------------------------------------------------
    int rblk = wid >> 1, cblk = wid & 1;
    int g = lane >> 2, tg = lane & 3;

    float acc[2][8][4];
#pragma unroll
    for (int mt = 0; mt < 2; mt++)
#pragma unroll
        for (int n = 0; n < 8; n++)
#pragma unroll
            for (int j = 0; j < 4; j++) acc[mt][n][j] = 0.f;

    const uint32_t* Usu = (const uint32_t*)Us;
#pragma unroll
    for (int k = 0; k < 16; k++) {
        int kc = k * 8 + tg;
        uint32_t a[2][4];
#pragma unroll
        for (int mt = 0; mt < 2; mt++) {
            const uint32_t* base = Usu + (rblk * 32 + mt * 16 + g) * US_STRIDE + kc;
            a[mt][0] = base[0];
            a[mt][1] = base[8 * US_STRIDE];
            a[mt][2] = base[4];
            a[mt][3] = base[8 * US_STRIDE + 4];
        }
        const uint32_t* brow0 = Wsu + kc * WS_STRIDE + cblk * 64 + g;
        const uint32_t* brow1 = brow0 + 4 * WS_STRIDE;
#pragma unroll
        for (int n = 0; n < 8; n++) {
            uint32_t bb0 = brow0[n * 8];
            uint32_t bb1 = brow1[n * 8];
            mma_tf32(acc[0][n], a[0], bb0, bb1);
            mma_tf32(acc[1][n], a[1], bb0, bb1);
        }
    }

    // --- epilogue: relu(+b1) . w2, quad reduce, cross-warp combine -----------
#pragma unroll
    for (int mt = 0; mt < 2; mt++) {
        float p0 = 0.f, p1 = 0.f;
#pragma unroll
        for (int n = 0; n < 8; n++) {
            int c0 = cblk * 64 + n * 8 + 2 * tg;
            float wv0 = w2s[c0], wv1 = w2s[c0 + 1];
            float bb0 = b1s[c0], bb1 = b1s[c0 + 1];
            p0 += fmaxf(acc[mt][n][0] + bb0, 0.f) * wv0 + fmaxf(acc[mt][n][1] + bb1, 0.f) * wv1;
            p1 += fmaxf(acc[mt][n][2] + bb0, 0.f) * wv0 + fmaxf(acc[mt][n][3] + bb1, 0.f) * wv1;
        }
        p0 += __shfl_xor_sync(0xffffffffu, p0, 1);
        p0 += __shfl_xor_sync(0xffffffffu, p0, 2);
        p1 += __shfl_xor_sync(0xffffffffu, p1, 1);
        p1 += __shfl_xor_sync(0xffffffffu, p1, 2);
        if (tg == 0) {
            int rr = rblk * 32 + mt * 16 + g;
            pbuf[cblk * 128 + rr] = p0;
            pbuf[cblk * 128 + rr + 8] = p1;
        }
    }
    __syncthreads();
    if (tid < 128) out[e0 + tid] = pbuf[tid] + pbuf[128 + tid] + b2[0];
}

// ---------------- launch -----------------------------------------------------
extern "C" void kernel_launch(void* const* d_in, const int* in_sizes, int n_in,
                              void* d_out, int out_size) {
    const float* x       = (const float*)d_in[0];
    const int*   ei      = (const int*)d_in[1];
    const float* convs_W = (const float*)d_in[2];
    const float* convs_b = (const float*)d_in[3];
    const float* fc0_W   = (const float*)d_in[4];
    const float* fc0_b   = (const float*)d_in[5];
    const float* fc1_W   = (const float*)d_in[6];
    const float* fc1_b   = (const float*)d_in[7];
    const float* fc2_W   = (const float*)d_in[8];
    const float* fc2_b   = (const float*)d_in[9];
    float* out = (float*)d_out;

    const int* row = ei;
    const int* col = ei + N_EDGES;

    const int SMEM_GEMM = (64 * 128 + 128 * 128) * 4;
    const int SMEM_EDGE = SMEM_EDGE_FLOATS * 4;
    cudaFuncSetAttribute(k_sgemm, cudaFuncAttributeMaxDynamicSharedMemorySize, SMEM_GEMM);
    cudaFuncSetAttribute(k_edge_mlp_mma, cudaFuncAttributeMaxDynamicSharedMemorySize, SMEM_EDGE);

    // 1. degree / dis / CSR
    k_zero_deg<<<(N_NODES + 255) / 256, 256>>>();
    k_count_deg<<<(N_EDGES + 255) / 256, 256>>>(col);
    k_scan_dis<<<1, 1024>>>();
    k_fill_csr<<<(N_EDGES + 255) / 256, 256>>>(row, col);

    // 2. GCN layers
    const int GRID_GEMM = (N_NODES + 63) / 64;
    for (int l = 0; l < N_LAYERS; l++) {
        const float* W = convs_W + l * CDIM * CDIM;
        const float* b = convs_b + l * CDIM;
        k_sgemm<<<GRID_GEMM, 256, SMEM_GEMM>>>(x, (l == 0) ? 0 : 1, 0, W, nullptr, N_NODES);
        k_agg<<<(N_NODES * 32 + 255) / 256, 256>>>(b, (l == 0) ? 0 : 1);
    }

    // 3. factorized fc0: A = h@W0a + b0, B = h@W0b
    k_sgemm<<<GRID_GEMM, 256, SMEM_GEMM>>>(nullptr, 1, 1, fc0_W, fc0_b, N_NODES);
    k_sgemm<<<GRID_GEMM, 256, SMEM_GEMM>>>(nullptr, 1, 2, fc0_W + CDIM * CDIM, nullptr, N_NODES);

    // 4. fused edge MLP on tensor cores (mma.sync tf32)
    k_edge_mlp_mma<<<N_EDGES / 128, 256, SMEM_EDGE>>>(row, col, fc1_W, fc1_b,
                                                      fc2_W, fc2_b, out);
}